// round 12
// baseline (speedup 1.0000x reference)
#include <cuda_runtime.h>
#include <cuda_fp16.h>

#define BB    16
#define NN    65536
#define CC    256
#define DINN  16
#define DOUTT 16

__device__ __align__(16) __half g_s[DINN * BB * CC];      // s: [i][b][k], fp16
__device__ __align__(16) float  g_wdt[CC * DOUTT * DINN]; // w_diag: [c][o][i]
__device__ __align__(16) float  g_off[BB * CC * DOUTT];   // off: [b][c][o]
__device__ unsigned char g_chunk[NN];                     // chunk id per row n

__device__ __forceinline__ float4 shfl_xor_f4(float4 v, int m) {
    v.x = __shfl_xor_sync(0xffffffffu, v.x, m);
    v.y = __shfl_xor_sync(0xffffffffu, v.y, m);
    v.z = __shfl_xor_sync(0xffffffffu, v.z, m);
    v.w = __shfl_xor_sync(0xffffffffu, v.w, m);
    return v;
}
__device__ __forceinline__ float dot4(float4 a, float4 b) {
    return a.x*b.x + a.y*b.y + a.z*b.z + a.w*b.w;
}
__device__ __forceinline__ void mma16816(float& d0, float& d1, float& d2, float& d3,
                                         unsigned a0, unsigned a1, unsigned a2, unsigned a3,
                                         unsigned b0, unsigned b1) {
    asm volatile(
        "mma.sync.aligned.m16n8k16.row.col.f32.f16.f16.f32 "
        "{%0,%1,%2,%3}, {%4,%5,%6,%7}, {%8,%9}, {%0,%1,%2,%3};\n"
        : "+f"(d0), "+f"(d1), "+f"(d2), "+f"(d3)
        : "r"(a0), "r"(a1), "r"(a2), "r"(a3), "r"(b0), "r"(b1));
}

// ---------------------------------------------------------------------------
// kT: transpose w_diag [o][i][c] -> [c][o*16+i]; build chunk map.
// ---------------------------------------------------------------------------
__global__ __launch_bounds__(256) void kT(const float* __restrict__ wdiag,
                                          const int* __restrict__ pid) {
    int idx = blockIdx.x * 256 + threadIdx.x;      // 65536 total
    int c  = idx & 255;
    int oi = idx >> 8;
    g_wdt[c * 256 + oi] = wdiag[idx];
    g_chunk[pid[idx]] = (unsigned char)(idx >> 8);
}

// ---------------------------------------------------------------------------
// kAC: fused gather: out[b, n, :] = W_c x + b1   AND   s reduction -> g_s.
// Identical dataflow to the proven kC (grid (C,B), 256 thr, q-split, shfl),
// plus per-thread acc over its 4 row-quarters and the R6 2-stage reduce tail.
// ---------------------------------------------------------------------------
__global__ __launch_bounds__(256, 3) void kAC(const float* __restrict__ x,
                                              const int* __restrict__ pid,
                                              const float* __restrict__ b1,
                                              float* __restrict__ out) {
    int c = blockIdx.x, b = blockIdx.y;
    int t = threadIdx.x;
    int q = t & 3, g = t >> 2;
    int warp = t >> 5, lane = t & 31;

    __shared__ float4 red[32];

    const int* pc = pid + c * 256;
    int ns[4];
    ns[0] = __ldg(pc + g);
    ns[1] = __ldg(pc + g + 64);
    ns[2] = __ldg(pc + g + 128);
    ns[3] = __ldg(pc + g + 192);

    float4 wreg[4][4];
    float  bs[4];
    const float* wc = g_wdt + c * 256;
#pragma unroll
    for (int oo = 0; oo < 4; oo++) {
        int o = 4 * q + oo;
        bs[oo] = __ldg(b1 + o);
#pragma unroll
        for (int p = 0; p < 4; p++)
            wreg[oo][p] = *(const float4*)(wc + o * 16 + 4 * (q ^ p));
    }

    const float* xb = x + (size_t)b * NN * DINN;
    float* ob = out + (size_t)b * NN * DOUTT;

    float4 acc = make_float4(0.f, 0.f, 0.f, 0.f);

#pragma unroll
    for (int j = 0; j < 4; j++) {
        int n = ns[j];
        float4 X0 = ((const float4*)(xb + (size_t)n * DINN))[q];
        acc.x += X0.x; acc.y += X0.y; acc.z += X0.z; acc.w += X0.w;
        float4 X1 = shfl_xor_f4(X0, 1);
        float4 X2 = shfl_xor_f4(X0, 2);
        float4 X3 = shfl_xor_f4(X0, 3);

        float r0 = bs[0], r1 = bs[1], r2 = bs[2], r3 = bs[3];
        r0 += dot4(wreg[0][0], X0) + dot4(wreg[0][1], X1) + dot4(wreg[0][2], X2) + dot4(wreg[0][3], X3);
        r1 += dot4(wreg[1][0], X0) + dot4(wreg[1][1], X1) + dot4(wreg[1][2], X2) + dot4(wreg[1][3], X3);
        r2 += dot4(wreg[2][0], X0) + dot4(wreg[2][1], X1) + dot4(wreg[2][2], X2) + dot4(wreg[2][3], X3);
        r3 += dot4(wreg[3][0], X0) + dot4(wreg[3][1], X1) + dot4(wreg[3][2], X2) + dot4(wreg[3][3], X3);

        ((float4*)(ob + (size_t)n * DOUTT))[q] = make_float4(r0, r1, r2, r3);
    }

    // s-reduction tail (R6 kA proven): 3 shfl rounds over g-bits, 2-stage.
#pragma unroll
    for (int m = 4; m < 32; m <<= 1) {
        float4 o = shfl_xor_f4(acc, m);
        acc.x += o.x; acc.y += o.y; acc.z += o.z; acc.w += o.w;
    }
    if (lane < 4) red[warp * 4 + lane] = acc;
    __syncthreads();
    if (t < 32) {
        float4 v = red[t];
#pragma unroll
        for (int m = 4; m < 32; m <<= 1) {
            float4 o = shfl_xor_f4(v, m);
            v.x += o.x; v.y += o.y; v.z += o.z; v.w += o.w;
        }
        if (t < 4) {
            int i0 = 4 * t;
            g_s[((i0 + 0) * BB + b) * CC + c] = __float2half(v.x);
            g_s[((i0 + 1) * BB + b) * CC + c] = __float2half(v.y);
            g_s[((i0 + 2) * BB + b) * CC + c] = __float2half(v.z);
            g_s[((i0 + 3) * BB + b) * CC + c] = __float2half(v.w);
        }
    }
}

// ---------------------------------------------------------------------------
// kB (R10 tensor-core, unchanged): per c, D[16b][16o] = s * w_off, f32 accum.
// ---------------------------------------------------------------------------
__global__ __launch_bounds__(256) void kB(const float* __restrict__ woff) {
    int c    = blockIdx.x;
    int t    = threadIdx.x;
    int w    = t >> 5;
    int lane = t & 31;
    int r    = lane >> 2;
    int cp   = (lane & 3) * 2;
    int W    = w * 32;

    __shared__ __align__(16) __half sh_s[16 * 256];
    __shared__ __align__(16) __half sh_w[16 * 256];
    __shared__ __align__(16) float  dred[8 * 256];

    int so[4], sk4[4];
#pragma unroll
    for (int rr = 0; rr < 4; rr++) {
        int F = t + 256 * rr;
        so[rr]  = F >> 6;
        sk4[rr] = F & 63;
    }

    float4 wbuf[4];
    uint4  sbuf0, sbuf1;
    const uint4* gs4 = (const uint4*)g_s;

#pragma unroll
    for (int rr = 0; rr < 4; rr++)
        wbuf[rr] = __ldg((const float4*)(woff + (((size_t)so[rr] * 16 + 0) * CC + c) * CC) + sk4[rr]);
    sbuf0 = gs4[t];
    sbuf1 = gs4[256 + t];

    float d0[4] = {0.f, 0.f, 0.f, 0.f};
    float d1[4] = {0.f, 0.f, 0.f, 0.f};

    for (int i = 0; i < 16; i++) {
#pragma unroll
        for (int rr = 0; rr < 4; rr++) {
            __half2 h0 = __floats2half2_rn(wbuf[rr].x, wbuf[rr].y);
            __half2 h1 = __floats2half2_rn(wbuf[rr].z, wbuf[rr].w);
            *(uint2*)&sh_w[so[rr] * 256 + sk4[rr] * 4] =
                make_uint2(*(unsigned*)&h0, *(unsigned*)&h1);
        }
        ((uint4*)sh_s)[t]       = sbuf0;
        ((uint4*)sh_s)[t + 256] = sbuf1;
        __syncthreads();

        if (i < 15) {
#pragma unroll
            for (int rr = 0; rr < 4; rr++)
                wbuf[rr] = __ldg((const float4*)(woff + (((size_t)so[rr] * 16 + (i + 1)) * CC + c) * CC) + sk4[rr]);
            sbuf0 = gs4[(i + 1) * 512 + t];
            sbuf1 = gs4[(i + 1) * 512 + 256 + t];
        }

#pragma unroll
        for (int ks = 0; ks < 2; ks++) {
            int kb = W + ks * 16 + cp;
            unsigned a0 = *(const unsigned*)&sh_s[r * 256 + kb];
            unsigned a1 = *(const unsigned*)&sh_s[(r + 8) * 256 + kb];
            unsigned a2 = *(const unsigned*)&sh_s[r * 256 + kb + 8];
            unsigned a3 = *(const unsigned*)&sh_s[(r + 8) * 256 + kb + 8];
            unsigned b00 = *(const unsigned*)&sh_w[r * 256 + kb];
            unsigned b01 = *(const unsigned*)&sh_w[r * 256 + kb + 8];
            unsigned b10 = *(const unsigned*)&sh_w[(8 + r) * 256 + kb];
            unsigned b11 = *(const unsigned*)&sh_w[(8 + r) * 256 + kb + 8];
            mma16816(d0[0], d0[1], d0[2], d0[3], a0, a1, a2, a3, b00, b01);
            mma16816(d1[0], d1[1], d1[2], d1[3], a0, a1, a2, a3, b10, b11);
        }
        __syncthreads();
    }

    *(float2*)&dred[w * 256 + r * 16 + cp]            = make_float2(d0[0], d0[1]);
    *(float2*)&dred[w * 256 + (r + 8) * 16 + cp]      = make_float2(d0[2], d0[3]);
    *(float2*)&dred[w * 256 + r * 16 + 8 + cp]        = make_float2(d1[0], d1[1]);
    *(float2*)&dred[w * 256 + (r + 8) * 16 + 8 + cp]  = make_float2(d1[2], d1[3]);
    __syncthreads();

    float sum = 0.f;
#pragma unroll
    for (int ww = 0; ww < 8; ww++) sum += dred[ww * 256 + t];
    int b = t >> 4, o = t & 15;
    g_off[((size_t)b * CC + c) * DOUTT + o] = sum * (1.0f / (float)NN);
}

// ---------------------------------------------------------------------------
// kE: linear epilogue: out[b, n, 4q..4q+3] += off[b, chunk[n], 4q..4q+3]
// grid (256, 16), 256 thr, 4 float4/thread. Fully coalesced; chunk map and
// per-b off slice (16 KB) are cache-resident.
// ---------------------------------------------------------------------------
__global__ __launch_bounds__(256) void kE(float* __restrict__ out) {
    int b = blockIdx.y;
    int t = threadIdx.x;
    float4* o4 = ((float4*)out) + ((size_t)b * NN * DINN) / 4 + (size_t)blockIdx.x * 1024;
    int nbase = blockIdx.x * 256;
    const float* offb = g_off + (size_t)b * CC * DOUTT;

    int ch[4];
#pragma unroll
    for (int u = 0; u < 4; u++) {
        int idx = u * 256 + t;
        ch[u] = __ldg(&g_chunk[nbase + (idx >> 2)]);
    }
#pragma unroll
    for (int u = 0; u < 4; u++) {
        int idx = u * 256 + t;
        int q = idx & 3;
        float4 ov = o4[idx];
        float4 f = *(const float4*)(offb + ch[u] * DOUTT + 4 * q);
        ov.x += f.x; ov.y += f.y; ov.z += f.z; ov.w += f.w;
        o4[idx] = ov;
    }
}

extern "C" void kernel_launch(void* const* d_in, const int* in_sizes, int n_in,
                              void* d_out, int out_size) {
    const float* x     = (const float*)d_in[0];
    const float* wdiag = (const float*)d_in[1];
    const float* woff  = (const float*)d_in[2];
    const float* b1    = (const float*)d_in[3];
    const int*   pid   = (const int*)d_in[4];
    float* out = (float*)d_out;

    kT<<<256, 256>>>(wdiag, pid);
    kAC<<<dim3(CC, BB), 256>>>(x, pid, b1, out);
    kB<<<CC, 256>>>(woff);
    kE<<<dim3(256, BB), 256>>>(out);
}

// round 14
// speedup vs baseline: 1.5274x; 1.5274x over previous
#include <cuda_runtime.h>
#include <cuda_fp16.h>

#define BB    16
#define NN    65536
#define CC    256
#define DINN  16
#define DOUTT 16

__device__ __align__(16) __half g_s[DINN * BB * CC];      // s: [i][b][k], fp16
__device__ __align__(16) float  g_wdt[CC * DOUTT * DINN]; // w_diag: [c][o][i]
__device__ __align__(16) float  g_off[BB * CC * DOUTT];   // off: [b][c][o]

__device__ __forceinline__ float4 shfl_xor_f4(float4 v, int m) {
    v.x = __shfl_xor_sync(0xffffffffu, v.x, m);
    v.y = __shfl_xor_sync(0xffffffffu, v.y, m);
    v.z = __shfl_xor_sync(0xffffffffu, v.z, m);
    v.w = __shfl_xor_sync(0xffffffffu, v.w, m);
    return v;
}
__device__ __forceinline__ float dot4(float4 a, float4 b) {
    return a.x*b.x + a.y*b.y + a.z*b.z + a.w*b.w;
}
__device__ __forceinline__ void mma16816(float& d0, float& d1, float& d2, float& d3,
                                         unsigned a0, unsigned a1, unsigned a2, unsigned a3,
                                         unsigned b0, unsigned b1) {
    asm volatile(
        "mma.sync.aligned.m16n8k16.row.col.f32.f16.f16.f32 "
        "{%0,%1,%2,%3}, {%4,%5,%6,%7}, {%8,%9}, {%0,%1,%2,%3};\n"
        : "+f"(d0), "+f"(d1), "+f"(d2), "+f"(d3)
        : "r"(a0), "r"(a1), "r"(a2), "r"(a3), "r"(b0), "r"(b1));
}

// ---------------------------------------------------------------------------
// kT: transpose w_diag [o][i][c] -> [c][o*16+i]; zero g_off for kB atomics.
// ---------------------------------------------------------------------------
__global__ __launch_bounds__(256) void kT(const float* __restrict__ wdiag) {
    int idx = blockIdx.x * 256 + threadIdx.x;      // 65536 total
    int c  = idx & 255;
    int oi = idx >> 8;
    g_wdt[c * 256 + oi] = wdiag[idx];
    g_off[idx] = 0.f;
}

// ---------------------------------------------------------------------------
// kA: s[i][b][c] = sum_r x[b, pid[c*256+r], i]   (R6 exact)
// ---------------------------------------------------------------------------
__global__ __launch_bounds__(256) void kA(const float* __restrict__ x,
                                          const int* __restrict__ pid) {
    int c = blockIdx.x, b = blockIdx.y;
    __shared__ int ids[256];
    __shared__ float4 red[32];
    int t = threadIdx.x;
    int q = t & 3, g = t >> 2;
    int warp = t >> 5, lane = t & 31;
    ids[t] = pid[c * 256 + t];
    __syncthreads();

    const float* xb = x + (size_t)b * NN * DINN;
    float4 acc = make_float4(0.f, 0.f, 0.f, 0.f);
#pragma unroll
    for (int j = 0; j < 4; j++) {
        int n = ids[g + 64 * j];
        float4 v = ((const float4*)(xb + (size_t)n * DINN))[q];
        acc.x += v.x; acc.y += v.y; acc.z += v.z; acc.w += v.w;
    }
#pragma unroll
    for (int m = 4; m < 32; m <<= 1) {
        float4 o = shfl_xor_f4(acc, m);
        acc.x += o.x; acc.y += o.y; acc.z += o.z; acc.w += o.w;
    }
    if (lane < 4) red[warp * 4 + lane] = acc;
    __syncthreads();
    if (t < 32) {
        float4 v = red[t];
#pragma unroll
        for (int m = 4; m < 32; m <<= 1) {
            float4 o = shfl_xor_f4(v, m);
            v.x += o.x; v.y += o.y; v.z += o.z; v.w += o.w;
        }
        if (t < 4) {
            int i0 = 4 * t;
            g_s[((i0 + 0) * BB + b) * CC + c] = __float2half(v.x);
            g_s[((i0 + 1) * BB + b) * CC + c] = __float2half(v.y);
            g_s[((i0 + 2) * BB + b) * CC + c] = __float2half(v.z);
            g_s[((i0 + 3) * BB + b) * CC + c] = __float2half(v.w);
        }
    }
}

// ---------------------------------------------------------------------------
// kB (tensor-core, k-split): grid (C, 2); block (c, y) owns k in [128y,128y+128).
// Warp w -> k-window [128y + 16w, +16): one m16n8k16 k-step x 2 n-halves per
// i-slice. w_off/s reads partitioned (no duplicate traffic). f32 accum;
// halves combined via atomicAdd into g_off (zeroed in kT).
// ---------------------------------------------------------------------------
__global__ __launch_bounds__(256) void kB(const float* __restrict__ woff) {
    int c    = blockIdx.x;
    int y    = blockIdx.y;
    int t    = threadIdx.x;
    int w    = t >> 5;
    int lane = t & 31;
    int r    = lane >> 2;          // 0..7
    int cp   = (lane & 3) * 2;     // 0,2,4,6
    int kb   = w * 16 + cp;        // within 128-wide window

    __shared__ __align__(16) __half sh_s[16 * 128];   // [b][kk]  4 KB
    __shared__ __align__(16) __half sh_w[16 * 128];   // [o][kk]  4 KB
    __shared__ __align__(16) float  dred[8 * 256];    // [w][b*16+o] 8 KB

    // s staging: t -> b = t>>4, k4 = t&15 ; one uint4 (8 halves)
    int sb_b  = t >> 4;
    int sb_k4 = t & 15;
    // w staging: rounds rr=0..1, F = t + 256*rr -> o = F>>5, k4 = F&31 (float4)
    int wo[2], wk4[2];
#pragma unroll
    for (int rr = 0; rr < 2; rr++) {
        int F = t + 256 * rr;
        wo[rr]  = F >> 5;
        wk4[rr] = F & 31;
    }

    const uint4* gs4 = (const uint4*)g_s;
    float4 wbuf[2];
    uint4  sbuf;

    // preload slice 0
#pragma unroll
    for (int rr = 0; rr < 2; rr++)
        wbuf[rr] = __ldg((const float4*)(woff + (((size_t)wo[rr] * 16 + 0) * CC + c) * CC + y * 128) + wk4[rr]);
    sbuf = gs4[sb_b * 32 + y * 16 + sb_k4];

    float d0[4] = {0.f, 0.f, 0.f, 0.f};
    float d1[4] = {0.f, 0.f, 0.f, 0.f};

    for (int i = 0; i < 16; i++) {
        // store staged slice i
#pragma unroll
        for (int rr = 0; rr < 2; rr++) {
            __half2 h0 = __floats2half2_rn(wbuf[rr].x, wbuf[rr].y);
            __half2 h1 = __floats2half2_rn(wbuf[rr].z, wbuf[rr].w);
            *(uint2*)&sh_w[wo[rr] * 128 + wk4[rr] * 4] =
                make_uint2(*(unsigned*)&h0, *(unsigned*)&h1);
        }
        ((uint4*)sh_s)[t] = sbuf;
        __syncthreads();

        // prefetch slice i+1
        if (i < 15) {
#pragma unroll
            for (int rr = 0; rr < 2; rr++)
                wbuf[rr] = __ldg((const float4*)(woff + (((size_t)wo[rr] * 16 + (i + 1)) * CC + c) * CC + y * 128) + wk4[rr]);
            sbuf = gs4[(i + 1) * 512 + sb_b * 32 + y * 16 + sb_k4];
        }

        // one k-step x 2 n-halves
        unsigned a0 = *(const unsigned*)&sh_s[r * 128 + kb];
        unsigned a1 = *(const unsigned*)&sh_s[(r + 8) * 128 + kb];
        unsigned a2 = *(const unsigned*)&sh_s[r * 128 + kb + 8];
        unsigned a3 = *(const unsigned*)&sh_s[(r + 8) * 128 + kb + 8];
        unsigned b00 = *(const unsigned*)&sh_w[r * 128 + kb];
        unsigned b01 = *(const unsigned*)&sh_w[r * 128 + kb + 8];
        unsigned b10 = *(const unsigned*)&sh_w[(8 + r) * 128 + kb];
        unsigned b11 = *(const unsigned*)&sh_w[(8 + r) * 128 + kb + 8];
        mma16816(d0[0], d0[1], d0[2], d0[3], a0, a1, a2, a3, b00, b01);
        mma16816(d1[0], d1[1], d1[2], d1[3], a0, a1, a2, a3, b10, b11);
        __syncthreads();
    }

    // write warp partials: D[b][o]
    *(float2*)&dred[w * 256 + r * 16 + cp]            = make_float2(d0[0], d0[1]);
    *(float2*)&dred[w * 256 + (r + 8) * 16 + cp]      = make_float2(d0[2], d0[3]);
    *(float2*)&dred[w * 256 + r * 16 + 8 + cp]        = make_float2(d1[0], d1[1]);
    *(float2*)&dred[w * 256 + (r + 8) * 16 + 8 + cp]  = make_float2(d1[2], d1[3]);
    __syncthreads();

    float sum = 0.f;
#pragma unroll
    for (int ww = 0; ww < 8; ww++) sum += dred[ww * 256 + t];
    int b = t >> 4, o = t & 15;
    atomicAdd(&g_off[((size_t)b * CC + c) * DOUTT + o], sum * (1.0f / (float)NN));
}

// ---------------------------------------------------------------------------
// kC (R6 exact, measured ~32us stable)
// ---------------------------------------------------------------------------
__global__ __launch_bounds__(256, 3) void kC(const float* __restrict__ x,
                                             const int* __restrict__ pid,
                                             const float* __restrict__ b1,
                                             float* __restrict__ out) {
    int c = blockIdx.x, b = blockIdx.y;
    int t = threadIdx.x;
    int q = t & 3, g = t >> 2;

    const int* pc = pid + c * 256;
    int ns[4];
    ns[0] = __ldg(pc + g);
    ns[1] = __ldg(pc + g + 64);
    ns[2] = __ldg(pc + g + 128);
    ns[3] = __ldg(pc + g + 192);

    float4 wreg[4][4];
    float  bs[4];
    const float* wc = g_wdt + c * 256;
#pragma unroll
    for (int oo = 0; oo < 4; oo++) {
        int o = 4 * q + oo;
        bs[oo] = __ldg(&g_off[((size_t)b * CC + c) * DOUTT + o]) + __ldg(b1 + o);
#pragma unroll
        for (int p = 0; p < 4; p++)
            wreg[oo][p] = *(const float4*)(wc + o * 16 + 4 * (q ^ p));
    }

    const float* xb = x + (size_t)b * NN * DINN;
    float* ob = out + (size_t)b * NN * DOUTT;

#pragma unroll
    for (int j = 0; j < 4; j++) {
        int n = ns[j];
        float4 X0 = ((const float4*)(xb + (size_t)n * DINN))[q];
        float4 X1 = shfl_xor_f4(X0, 1);
        float4 X2 = shfl_xor_f4(X0, 2);
        float4 X3 = shfl_xor_f4(X0, 3);

        float r0 = bs[0], r1 = bs[1], r2 = bs[2], r3 = bs[3];
        r0 += dot4(wreg[0][0], X0) + dot4(wreg[0][1], X1) + dot4(wreg[0][2], X2) + dot4(wreg[0][3], X3);
        r1 += dot4(wreg[1][0], X0) + dot4(wreg[1][1], X1) + dot4(wreg[1][2], X2) + dot4(wreg[1][3], X3);
        r2 += dot4(wreg[2][0], X0) + dot4(wreg[2][1], X1) + dot4(wreg[2][2], X2) + dot4(wreg[2][3], X3);
        r3 += dot4(wreg[3][0], X0) + dot4(wreg[3][1], X1) + dot4(wreg[3][2], X2) + dot4(wreg[3][3], X3);

        ((float4*)(ob + (size_t)n * DOUTT))[q] = make_float4(r0, r1, r2, r3);
    }
}

extern "C" void kernel_launch(void* const* d_in, const int* in_sizes, int n_in,
                              void* d_out, int out_size) {
    const float* x     = (const float*)d_in[0];
    const float* wdiag = (const float*)d_in[1];
    const float* woff  = (const float*)d_in[2];
    const float* b1    = (const float*)d_in[3];
    const int*   pid   = (const int*)d_in[4];
    float* out = (float*)d_out;

    kT<<<256, 256>>>(wdiag);
    kA<<<dim3(CC, BB), 256>>>(x, pid);
    kB<<<dim3(CC, 2), 256>>>(woff);
    kC<<<dim3(CC, BB), 256>>>(x, pid, b1, out);
}